// round 17
// baseline (speedup 1.0000x reference)
#include <cuda_runtime.h>
#include <cuda_fp16.h>
#include <cstdint>
#include <math.h>

#define BB 8
#define NN 2048
#define DD 128
#define KK 64
#define ROWS 128    // rows per CTA
#define TILES 16    // NN / ROWS

// per-tile partials (fully rewritten every launch -> no zero kernel)
__device__ float g_Pp[BB * TILES * KK * DD];   // 4 MB (L2-resident)
__device__ float g_sp[BB * TILES * KK];
__device__ unsigned int g_arr[BB];             // reset by finalizer each launch

// half strides: all matrices 136 halves/row (68 words -> conflict-free ldmatrix)
#define STRC 136
#define STRA 136

// smem byte offsets
#define O_CS   0                        // 64*136*2  = 17408
#define O_XS   17408                    // 128*136*2 = 34816
#define O_AT   52224                    // 64*136*2  = 17408
#define O_CN2  69632                    // 64 floats
#define O_SSM  69888                    // 64 floats
#define O_FLG  70144                    // 1 int
#define SMEMB  70208

// ---- FFMA-only transcendentals (avoid the 0.5 op/cyc/SM MUFU pipe) ----
__device__ __forceinline__ float fexp(float x) {      // e^x, |x| small here
    float y = x * 1.4426950408889634f;
    float t = y + 12582912.f;
    int j = __float_as_int(t) << 23;
    float f = y - (t - 12582912.f);
    float p = 1.3333558e-3f;
    p = fmaf(p, f, 9.6181291e-3f);
    p = fmaf(p, f, 5.5504109e-2f);
    p = fmaf(p, f, 2.4022648e-1f);
    p = fmaf(p, f, 6.9314718e-1f);
    p = fmaf(p, f, 1.0f);
    return __int_as_float(__float_as_int(p) + j);
}
__device__ __forceinline__ float frsqrt(float s) {
    float h = __int_as_float(0x5f375a86 - (__float_as_int(s) >> 1));
    h = h * fmaf(-0.5f * s, h * h, 1.5f);
    h = h * fmaf(-0.5f * s, h * h, 1.5f);
    return h;
}
__device__ __forceinline__ float frcp(float s) {
    float r = __int_as_float(0x7ef311c3 - __float_as_int(s));
    r = r * fmaf(-s, r, 2.0f);
    r = r * fmaf(-s, r, 2.0f);
    return r;
}

__device__ __forceinline__ void mma16(float* d, const uint32_t* a, const uint32_t* b) {
    asm volatile(
        "mma.sync.aligned.m16n8k16.row.col.f32.f16.f16.f32 "
        "{%0,%1,%2,%3}, {%4,%5,%6,%7}, {%8,%9}, {%0,%1,%2,%3};"
        : "+f"(d[0]), "+f"(d[1]), "+f"(d[2]), "+f"(d[3])
        : "r"(a[0]), "r"(a[1]), "r"(a[2]), "r"(a[3]), "r"(b[0]), "r"(b[1]));
}
#define LDSM4(r, addr) \
    asm volatile("ldmatrix.sync.aligned.m8n8.x4.shared.b16 {%0,%1,%2,%3}, [%4];" \
        : "=r"((r)[0]), "=r"((r)[1]), "=r"((r)[2]), "=r"((r)[3]) : "r"(addr))

// ---------------------------------------------------------------------------
// Fused kernel: grid = (16 tiles, 8 b) = 128 CTAs x 512 threads, 1 CTA/SM.
// Phase 1: GEMM1 over all 128 rows (warp w: n in [8w,8w+8)), softmax,
// GEMM2 (warp w: d in [8w,8w+8)), ONE partial store, fence, arrive.
// Last arriver per b finalizes all 64 k's warp-locally; others exit.
// ---------------------------------------------------------------------------
__global__ void __launch_bounds__(512, 1)
nv_main(const float* __restrict__ x, const float* __restrict__ cent,
        float* __restrict__ out) {
    extern __shared__ char smc[];
    half*  xs  = (half*)(smc + O_XS);
    half*  At  = (half*)(smc + O_AT);
    float* cn2 = (float*)(smc + O_CN2);
    float* ssm = (float*)(smc + O_SSM);
    int*   flg = (int*)(smc + O_FLG);
    const uint32_t sb = (uint32_t)__cvta_generic_to_shared(smc);

    const int tid = threadIdx.x, w = tid >> 5, l = tid & 31;
    const int g = l >> 2, t = l & 3;           // mma groupID / thread-in-group
    const int b = blockIdx.y, tile = blockIdx.x;
    const int nb = w * 8;

    if (tid < 64) ssm[tid] = 0.f;

    // ---- phase A: convert C -> fp16 smem; load+norm 128 x rows (8/warp) ----
    {
        half* Cs = (half*)(smc + O_CS);
        const float4* c4 = (const float4*)cent;
        const float4* x4 = (const float4*)(x + ((size_t)b * NN + (size_t)tile * ROWS) * DD);

        float4 xv[8];
        #pragma unroll
        for (int i = 0; i < 8; i++) xv[i] = x4[(w * 8 + i) * 32 + l];

        #pragma unroll
        for (int i = tid; i < KK * DD / 4; i += 512) {
            float4 v = c4[i];
            int k = i >> 5, d4 = (i & 31) * 4;
            *(half2*)&Cs[k * STRC + d4]     = __floats2half2_rn(v.x, v.y);
            *(half2*)&Cs[k * STRC + d4 + 2] = __floats2half2_rn(v.z, v.w);
        }

        #pragma unroll
        for (int i = 0; i < 8; i++) {
            float4 v = xv[i];
            float ss = v.x * v.x + v.y * v.y + v.z * v.z + v.w * v.w;
            #pragma unroll
            for (int o = 16; o; o >>= 1) ss += __shfl_xor_sync(~0u, ss, o);
            float ri = frsqrt(fmaxf(ss, 1e-24f));
            int r = w * 8 + i;
            *(half2*)&xs[r * STRC + 4 * l]     = __floats2half2_rn(v.x * ri, v.y * ri);
            *(half2*)&xs[r * STRC + 4 * l + 2] = __floats2half2_rn(v.z * ri, v.w * ri);
        }
    }
    __syncthreads();

    // ---- cn2[k] = ||c_k||^2 from rounded halves ----
    if (tid < 128) {
        const half* Cs = (const half*)(smc + O_CS);
        int kc = tid >> 1, q = tid & 1;
        float s = 0.f;
        #pragma unroll
        for (int j = 0; j < 32; j++) {
            float2 f = __half22float2(*(const half2*)&Cs[kc * STRC + q * 64 + 2 * j]);
            s += f.x * f.x + f.y * f.y;
        }
        s += __shfl_xor_sync(~0u, s, 1);
        if (q == 0) cn2[kc] = s;
    }
    __syncthreads();

    // ---- GEMM1: S^T[k][n] = C * xn^T, ALL 128 n at once (warp w: [8w,8w+8)) ----
    const uint32_t aAddr1 = sb + O_CS + (uint32_t)((l & 15) * 272 + (l >> 4) * 16);
    const uint32_t aAddr2 = sb + O_AT + (uint32_t)((l & 15) * 272 + (l >> 4) * 16);
    {
        const uint32_t* Xw = (const uint32_t*)xs;
        float acc[4][4];
        #pragma unroll
        for (int mt = 0; mt < 4; mt++)
            #pragma unroll
            for (int q = 0; q < 4; q++) acc[mt][q] = 0.f;

        #pragma unroll
        for (int s = 0; s < 8; s++) {
            uint32_t a[4][4], bf[2];
            #pragma unroll
            for (int mt = 0; mt < 4; mt++)
                LDSM4(a[mt], aAddr1 + mt * 4352 + s * 32);
            int bb2 = (nb + g) * 68 + 8 * s + t;
            bf[0] = Xw[bb2];
            bf[1] = Xw[bb2 + 4];
            #pragma unroll
            for (int mt = 0; mt < 4; mt++) mma16(acc[mt], a[mt], bf);
        }

        // softmax per n-column over k=64 (args tiny -> no max shift)
        float s0 = 0.f, s1 = 0.f;
        #pragma unroll
        for (int mt = 0; mt < 4; mt++) {
            float cA = cn2[mt * 16 + g], cB = cn2[mt * 16 + g + 8];
            acc[mt][0] = fexp(fmaf(-2.f, acc[mt][0], cA));
            acc[mt][1] = fexp(fmaf(-2.f, acc[mt][1], cA));
            acc[mt][2] = fexp(fmaf(-2.f, acc[mt][2], cB));
            acc[mt][3] = fexp(fmaf(-2.f, acc[mt][3], cB));
            s0 += acc[mt][0] + acc[mt][2];
            s1 += acc[mt][1] + acc[mt][3];
        }
        #pragma unroll
        for (int o = 4; o <= 16; o <<= 1) {
            s0 += __shfl_xor_sync(~0u, s0, o);
            s1 += __shfl_xor_sync(~0u, s1, o);
        }
        s0 = frcp(s0);
        s1 = frcp(s1);

        // assign -> At[k][n] (fp16) + row sums -> ssm
        #pragma unroll
        for (int mt = 0; mt < 4; mt++) {
            float a0 = acc[mt][0] * s0, a1 = acc[mt][1] * s1;
            float a2 = acc[mt][2] * s0, a3 = acc[mt][3] * s1;
            float rs0 = a0 + a1, rs1 = a2 + a3;
            int rr = mt * 16 + g, cc = nb + 2 * t;
            *(half2*)&At[rr * STRA + cc]       = __floats2half2_rn(a0, a1);
            *(half2*)&At[(rr + 8) * STRA + cc] = __floats2half2_rn(a2, a3);
            rs0 += __shfl_xor_sync(~0u, rs0, 1);
            rs0 += __shfl_xor_sync(~0u, rs0, 2);
            rs1 += __shfl_xor_sync(~0u, rs1, 1);
            rs1 += __shfl_xor_sync(~0u, rs1, 2);
            if (t == 0) {
                atomicAdd(&ssm[rr], rs0);
                atomicAdd(&ssm[rr + 8], rs1);
            }
        }
    }
    __syncthreads();

    // ---- GEMM2: P[k][d] = At[k][n] * Xn[n][d] over 128 n; warp w: d [8w,8w+8) ----
    float pc[4][4];
    #pragma unroll
    for (int mt = 0; mt < 4; mt++)
        #pragma unroll
        for (int q = 0; q < 4; q++) pc[mt][q] = 0.f;
    {
        const unsigned short* Xu = (const unsigned short*)xs;
        #pragma unroll
        for (int s = 0; s < 8; s++) {
            uint32_t a[4][4];
            #pragma unroll
            for (int mt = 0; mt < 4; mt++)
                LDSM4(a[mt], aAddr2 + mt * 4352 + s * 32);
            int dcol = nb + g;
            int rh = (16 * s + 2 * t) * STRC + dcol;
            uint32_t lo0 = Xu[rh],            hi0 = Xu[rh + STRC];
            uint32_t lo1 = Xu[rh + 8 * STRC], hi1 = Xu[rh + 9 * STRC];
            uint32_t bfr[2] = { lo0 | (hi0 << 16), lo1 | (hi1 << 16) };
            #pragma unroll
            for (int mt = 0; mt < 4; mt++) mma16(pc[mt], a[mt], bfr);
        }
    }

    // ---- ONE partial store (warp w: d cols [8w, 8w+8)) ----
    {
        float* Pb = g_Pp + (size_t)(b * TILES + tile) * KK * DD;
        #pragma unroll
        for (int mt = 0; mt < 4; mt++) {
            int rr = mt * 16 + g, dd2 = nb + 2 * t;
            *(float2*)&Pb[rr * DD + dd2]       = make_float2(pc[mt][0], pc[mt][1]);
            *(float2*)&Pb[(rr + 8) * DD + dd2] = make_float2(pc[mt][2], pc[mt][3]);
        }
        if (tid < 64) g_sp[(b * TILES + tile) * KK + tid] = ssm[tid];
    }

    // ========== arrive; last arriver per b finalizes, others exit ==========
    __threadfence();
    __syncthreads();
    if (tid == 0) {
        unsigned int my = atomicAdd(&g_arr[b], 1u);
        *flg = (my == TILES - 1) ? 1 : 0;
    }
    __syncthreads();
    if (*flg == 0) return;

    if (tid == 0) g_arr[b] = 0u;   // reset for next graph replay (sole owner now)
    __threadfence();               // acquire: order partial reads after the count

    // ========== finalize all 64 k of this b: warp w owns k in [4w, 4w+4) ====
    {
        const float4* P4 = (const float4*)g_Pp;
        const float4* c4 = (const float4*)cent;
        float4* o4 = (float4*)out;

        for (int kq = 0; kq < 4; kq++) {
            const int k = 4 * w + kq;

            float4 a = make_float4(0.f, 0.f, 0.f, 0.f);
            #pragma unroll
            for (int tt = 0; tt < TILES; tt++) {
                float4 v = __ldcg(&P4[((size_t)(b * TILES + tt) * KK + k) * 32 + l]);
                a.x += v.x; a.y += v.y; a.z += v.z; a.w += v.w;
            }

            float sv = (l < TILES) ? __ldcg(&g_sp[(b * TILES + l) * KK + k]) : 0.f;
            #pragma unroll
            for (int o = 8; o; o >>= 1) sv += __shfl_xor_sync(~0u, sv, o);
            float sk = __shfl_sync(~0u, sv, 0);

            float4 c = c4[k * 32 + l];
            float4 v = make_float4(fmaf(-sk, c.x, a.x), fmaf(-sk, c.y, a.y),
                                   fmaf(-sk, c.z, a.z), fmaf(-sk, c.w, a.w));
            float ssq = v.x * v.x + v.y * v.y + v.z * v.z + v.w * v.w;
            #pragma unroll
            for (int o = 16; o; o >>= 1) ssq += __shfl_xor_sync(~0u, ssq, o);
            float sc = 0.125f * frsqrt(fmaxf(ssq, 1e-24f));  // exact global norm = 8
            v.x *= sc; v.y *= sc; v.z *= sc; v.w *= sc;
            o4[((size_t)b * KK + k) * 32 + l] = v;
        }
    }
}

// ---------------------------------------------------------------------------
extern "C" void kernel_launch(void* const* d_in, const int* in_sizes, int n_in,
                              void* d_out, int out_size) {
    (void)in_sizes; (void)n_in; (void)out_size;
    const float* x    = (const float*)d_in[0];
    const float* cent = (const float*)d_in[1];
    float* out        = (float*)d_out;

    cudaFuncSetAttribute(nv_main, cudaFuncAttributeMaxDynamicSharedMemorySize, SMEMB);
    nv_main<<<dim3(TILES, BB), 512, SMEMB>>>(x, cent, out);
}